// round 15
// baseline (speedup 1.0000x reference)
#include <cuda_runtime.h>

#define IN_DIM 768
#define OUT_DIM 768
#define BATCH 32
#define NUMF 8
#define NROWS 9                    // 8 sin rows + 1 silu row

#define CHUNK 8                    // i's per split
#define O_TILE 128
#define THREADS 256                // 8 warps: bg = warp&3 (8 b), jh = warp>>2 (o-half)
#define WSTRIDE 68                 // floats/row; 68%32==4 -> lanes tile all banks

// per-buffer layout inside dynamic smem (bytes)
#define OFF_STILE 0                // 9216 B
#define OFF_WTILE 9216             // 34816 B
#define OFF_SBT   44032            // 4608 B (stride-9 rows)
#define BUF_BYTES 48640
#define SMEM_TOTAL (2 * BUF_BYTES) // 97280 B

typedef unsigned long long u64;

// ---- f32x2 helpers ----
__device__ __forceinline__ u64 pk2(float v) {
    u64 r; asm("mov.b64 %0, {%1, %1};" : "=l"(r) : "f"(v)); return r;
}
__device__ __forceinline__ u64 pk2ab(float a, float b) {
    u64 r; asm("mov.b64 %0, {%1, %2};" : "=l"(r) : "f"(a), "f"(b)); return r;
}
__device__ __forceinline__ void upk2(u64 v, float& lo, float& hi) {
    asm("mov.b64 {%0, %1}, %2;" : "=f"(lo), "=f"(hi) : "l"(v));
}
__device__ __forceinline__ void fma2(u64& d, u64 a, u64 b) {
    asm("fma.rn.f32x2 %0, %1, %2, %0;" : "+l"(d) : "l"(a), "l"(b));
}
__device__ __forceinline__ u64 mul2(u64 a, u64 b) {
    u64 r; asm("mul.rn.f32x2 %0, %1, %2;" : "=l"(r) : "l"(a), "l"(b)); return r;
}
__device__ __forceinline__ void redg_f32(float* addr, float v) {
    asm volatile("red.global.add.f32 [%0], %1;" :: "l"(addr), "f"(v) : "memory");
}

// ---- basis for one split into stile (1 column per thread; 256 = CHUNK*BATCH) ----
__device__ __forceinline__ void stage_basis(const float* __restrict__ x,
                                            const float* __restrict__ grid,
                                            int i0, float* stile, int tid) {
    int ii = tid >> 5;
    int b = tid & 31;
    float xv = x[b * IN_DIM + i0 + ii];
    float* col = stile + ii * (NROWS * BATCH) + b;

    float theta = __ldg(grid) * xv;
    float s1 = __sinf(theta);
    float c2 = 2.0f * __cosf(theta);
    float sm1 = s1, sm2 = 0.0f;
    col[0] = s1;
#pragma unroll
    for (int k = 1; k < NUMF; k++) {
        float sk = fmaf(c2, sm1, -sm2);
        sm2 = sm1; sm1 = sk;
        col[k * BATCH] = sk;
    }
    col[NUMF * BATCH] = xv / (1.0f + __expf(-xv));   // silu
}

// ---- one split's GEMM contribution (R12-proven inner loop) ----
__device__ __forceinline__ void compute_buf(const float* stile, const float* wtile,
                                            const float* sbtile,
                                            int lane, int jh, int b0,
                                            u64 acc[2][4]) {
    const float* sbase = stile + b0;
#pragma unroll 2
    for (int ii = 0; ii < CHUNK; ii++) {
        const float* srow = sbase + ii * (NROWS * BATCH);
#pragma unroll
        for (int half = 0; half < 2; half++) {
            float4 w4[2];
#pragma unroll
            for (int j = 0; j < 2; j++)
                w4[j] = *reinterpret_cast<const float4*>(
                    wtile + ((jh * 2 + j) * 32 + lane) * WSTRIDE + ii * 8 + half * 4);
#pragma unroll
            for (int kk = 0; kk < 4; kk++) {
                int k = half * 4 + kk;
                const double2* s2p = reinterpret_cast<const double2*>(srow + k * BATCH);
                double2 sa = s2p[0], sb = s2p[1];        // warp-uniform -> broadcast
                u64 s[4] = {__double_as_longlong(sa.x), __double_as_longlong(sa.y),
                            __double_as_longlong(sb.x), __double_as_longlong(sb.y)};
#pragma unroll
                for (int j = 0; j < 2; j++) {
                    float wv = (kk == 0) ? w4[j].x : (kk == 1) ? w4[j].y
                             : (kk == 2) ? w4[j].z : w4[j].w;
                    u64 wk = pk2(wv);
#pragma unroll
                    for (int p = 0; p < 4; p++) fma2(acc[j][p], wk, s[p]);
                }
            }
        }
        {   // silu row with scale_base weights
            const double2* s2p = reinterpret_cast<const double2*>(srow + NUMF * BATCH);
            double2 sa = s2p[0], sb = s2p[1];
            u64 s[4] = {__double_as_longlong(sa.x), __double_as_longlong(sa.y),
                        __double_as_longlong(sb.x), __double_as_longlong(sb.y)};
#pragma unroll
            for (int j = 0; j < 2; j++) {
                u64 wb = pk2(sbtile[((jh * 2 + j) * 32 + lane) * 9 + ii]);
#pragma unroll
                for (int p = 0; p < 4; p++) fma2(acc[j][p], wb, s[p]);
            }
        }
    }
}

// -------- pipelined kernel: 2 splits/block, register-staged prefetch --------
__global__ __launch_bounds__(THREADS, 2) void gemm_kernel(
    const float* __restrict__ x,
    const float* __restrict__ grid,
    const float* __restrict__ coef,
    const float* __restrict__ scale_sp,
    const float* __restrict__ scale_base,
    const float* __restrict__ bias_w,
    float* __restrict__ y) {

    extern __shared__ __align__(16) char dsm[];
    int tid = threadIdx.x;
    int lane = tid & 31;
    int warp = tid >> 5;
    int oBase = blockIdx.x * O_TILE;
    int s0 = blockIdx.y * 2;                  // splits s0, s0+1
    int i0a = s0 * CHUNK;
    int i0b = i0a + CHUNK;

    float* stile0 = reinterpret_cast<float*>(dsm + OFF_STILE);
    float* wtile0 = reinterpret_cast<float*>(dsm + OFF_WTILE);
    float* sbt0   = reinterpret_cast<float*>(dsm + OFF_SBT);
    float* stile1 = reinterpret_cast<float*>(dsm + BUF_BYTES + OFF_STILE);
    float* wtile1 = reinterpret_cast<float*>(dsm + BUF_BYTES + OFF_WTILE);
    float* sbt1   = reinterpret_cast<float*>(dsm + BUF_BYTES + OFF_SBT);

    // ---- stage split A into buf0 ----
    stage_basis(x, grid, i0a, stile0, tid);
#pragma unroll
    for (int g = 0; g < 4; g++) {             // 4 granules/thread
        int f = tid + g * THREADS;
        int o_l = f >> 3;
        int i_l = f & 7;
        int idx = (oBase + o_l) * IN_DIM + i0a + i_l;
        float4 c0 = reinterpret_cast<const float4*>(coef)[idx * 2];
        float4 c1 = reinterpret_cast<const float4*>(coef)[idx * 2 + 1];
        u64 sp2 = pk2(__ldg(scale_sp + idx));
        u64* wp = reinterpret_cast<u64*>(wtile0 + o_l * WSTRIDE + i_l * 8);
        wp[0] = mul2(pk2ab(c0.x, c0.y), sp2);
        wp[1] = mul2(pk2ab(c0.z, c0.w), sp2);
        wp[2] = mul2(pk2ab(c1.x, c1.y), sp2);
        wp[3] = mul2(pk2ab(c1.z, c1.w), sp2);
        sbt0[o_l * 9 + i_l] = __ldg(scale_base + idx);
    }
    __syncthreads();

    // ---- prefetch split B: LDGs into registers (overlap with compute A) ----
    float4 pc0[4], pc1[4];
    float psp[4], psb[4];
#pragma unroll
    for (int g = 0; g < 4; g++) {
        int f = tid + g * THREADS;
        int o_l = f >> 3;
        int i_l = f & 7;
        int idx = (oBase + o_l) * IN_DIM + i0b + i_l;
        pc0[g] = reinterpret_cast<const float4*>(coef)[idx * 2];
        pc1[g] = reinterpret_cast<const float4*>(coef)[idx * 2 + 1];
        psp[g] = __ldg(scale_sp + idx);
        psb[g] = __ldg(scale_base + idx);
    }
    stage_basis(x, grid, i0b, stile1, tid);    // MUFU + STS into buf1 (no reader yet)

    int bg = warp & 3;
    int jh = warp >> 2;
    int b0 = bg * 8;

    u64 acc[2][4];
#pragma unroll
    for (int j = 0; j < 2; j++)
#pragma unroll
        for (int p = 0; p < 4; p++) acc[j][p] = 0ULL;

    // ---- compute split A (DRAM for split B streams underneath) ----
    compute_buf(stile0, wtile0, sbt0, lane, jh, b0, acc);

    // ---- store prefetched split B, then compute it into the same acc ----
#pragma unroll
    for (int g = 0; g < 4; g++) {
        int f = tid + g * THREADS;
        int o_l = f >> 3;
        int i_l = f & 7;
        u64 sp2 = pk2(psp[g]);
        u64* wp = reinterpret_cast<u64*>(wtile1 + o_l * WSTRIDE + i_l * 8);
        wp[0] = mul2(pk2ab(pc0[g].x, pc0[g].y), sp2);
        wp[1] = mul2(pk2ab(pc0[g].z, pc0[g].w), sp2);
        wp[2] = mul2(pk2ab(pc1[g].x, pc1[g].y), sp2);
        wp[3] = mul2(pk2ab(pc1[g].z, pc1[g].w), sp2);
        sbt1[o_l * 9 + i_l] = psb[g];
    }
    __syncthreads();

    compute_buf(stile1, wtile1, sbt1, lane, jh, b0, acc);

    // ---- single epilogue: coalesced scalar reductions into y (half the REDG) ----
#pragma unroll
    for (int j = 0; j < 2; j++) {
        int o = oBase + (jh * 2 + j) * 32 + lane;
        float bw = (blockIdx.y == 0) ? __ldg(bias_w + o) : 0.0f;
#pragma unroll
        for (int p = 0; p < 4; p++) {
            float lo, hi;
            upk2(acc[j][p], lo, hi);
            redg_f32(y + (b0 + 2 * p) * OUT_DIM + o, lo + bw);
            redg_f32(y + (b0 + 2 * p + 1) * OUT_DIM + o, hi + bw);
        }
    }
}

extern "C" void kernel_launch(void* const* d_in, const int* in_sizes, int n_in,
                              void* d_out, int out_size) {
    // metadata order: x, grid, coef, bias_w, scale_base, scale_sp
    const float* x          = (const float*)d_in[0];
    const float* grid       = (const float*)d_in[1];
    const float* coef       = (const float*)d_in[2];
    const float* bias_w     = (const float*)d_in[3];
    const float* scale_base = (const float*)d_in[4];
    const float* scale_sp   = (const float*)d_in[5];
    float* y = (float*)d_out;

    cudaFuncSetAttribute(gemm_kernel,
                         cudaFuncAttributeMaxDynamicSharedMemorySize, SMEM_TOTAL);
    cudaMemsetAsync(y, 0, (size_t)out_size * sizeof(float));
    dim3 g(OUT_DIM / O_TILE, 48);       // 6 x 48 = 288 blocks, ~2/SM
    gemm_kernel<<<g, THREADS, SMEM_TOTAL>>>(x, grid, coef, scale_sp,
                                            scale_base, bias_w, y);
}

// round 16
// speedup vs baseline: 1.0101x; 1.0101x over previous
#include <cuda_runtime.h>

#define IN_DIM 768
#define OUT_DIM 768
#define BATCH 32
#define NUMF 8
#define NROWS 9                    // 8 sin + 1 silu terms per i

#define CHUNK 8                    // i's per block
#define NSPLIT 96
#define O_TILE 128
#define THREADS 256                // 8 warps = 8 m16 bands
#define KT (CHUNK * NROWS)         // 72 = 9 k8-steps exactly
#define ASTRIDE 76                 // (12*gid + tidq) mod 32 all-distinct -> conflict-free A frags
#define BSTRIDE 40                 // (8*tidq + gid) mod 32 all-distinct -> conflict-free B frags

// smem offsets (u32 units)
#define OFF_AHI 0
#define OFF_ALO (O_TILE * ASTRIDE)            // 9728
#define OFF_BHI (2 * O_TILE * ASTRIDE)        // 19456
#define OFF_BLO (OFF_BHI + KT * BSTRIDE)      // 19456 + 2880
#define SMEM_U32 (OFF_BLO + KT * BSTRIDE)     // 25216
#define SMEM_BYTES (SMEM_U32 * 4)             // 100864 B -> 2 blocks/SM

typedef unsigned int u32;

__device__ __forceinline__ u32 to_tf32(float v) {
    u32 r; asm("cvt.rna.tf32.f32 %0, %1;" : "=r"(r) : "f"(v)); return r;
}
__device__ __forceinline__ void split_store(u32* sm_hi, u32* sm_lo, int idx, float v) {
    u32 hi = to_tf32(v);
    float lo = v - __uint_as_float(hi);
    sm_hi[idx] = hi;
    sm_lo[idx] = to_tf32(lo);
}
__device__ __forceinline__ void mma_tf32(float c[4], const u32 a[4], u32 b0, u32 b1) {
    asm volatile(
        "mma.sync.aligned.m16n8k8.row.col.f32.tf32.tf32.f32 "
        "{%0,%1,%2,%3}, {%4,%5,%6,%7}, {%8,%9}, {%0,%1,%2,%3};"
        : "+f"(c[0]), "+f"(c[1]), "+f"(c[2]), "+f"(c[3])
        : "r"(a[0]), "r"(a[1]), "r"(a[2]), "r"(a[3]), "r"(b0), "r"(b1));
}
__device__ __forceinline__ void redg_f32(float* addr, float v) {
    asm volatile("red.global.add.f32 [%0], %1;" :: "l"(addr), "f"(v) : "memory");
}

// -------- fused kernel: basis + tf32-split staging + mma.sync GEMM + REDG --------
// Block = 128 o x 32 b x 8 i (K=72). Warp = one m16 o-band; tiles n8 x 4.
__global__ __launch_bounds__(THREADS, 2) void mma_kernel(
    const float* __restrict__ x,
    const float* __restrict__ grid,
    const float* __restrict__ coef,
    const float* __restrict__ scale_sp,
    const float* __restrict__ scale_base,
    const float* __restrict__ bias_w,
    float* __restrict__ y) {

    extern __shared__ __align__(16) u32 sm[];
    int tid = threadIdx.x;
    int lane = tid & 31;
    int warp = tid >> 5;
    int split = blockIdx.y;
    int i0 = split * CHUNK;
    int oBase = blockIdx.x * O_TILE;

    // ---- B staging: basis, one (i, b) column per thread (256 = CHUNK*BATCH) ----
    {
        int ii = tid >> 5;
        int b = tid & 31;
        float xv = x[b * IN_DIM + i0 + ii];
        float theta = __ldg(grid) * xv;
        float vals[NROWS];
        vals[0] = __sinf(theta);
        float c2 = 2.0f * __cosf(theta);
        float sm1 = vals[0], sm2 = 0.0f;
#pragma unroll
        for (int k = 1; k < NUMF; k++) {
            float sk = fmaf(c2, sm1, -sm2);
            sm2 = sm1; sm1 = sk;
            vals[k] = sk;
        }
        vals[8] = xv / (1.0f + __expf(-xv));          // silu
#pragma unroll
        for (int r = 0; r < NROWS; r++) {
            int k = ii * NROWS + r;                   // K index
            split_store(sm + OFF_BHI, sm + OFF_BLO, k * BSTRIDE + b, vals[r]);
        }
    }

    // ---- A staging: w = coef*scale_sp (r 0..7), scale_base (r 8); 4 granules/thread ----
#pragma unroll
    for (int g = 0; g < 4; g++) {
        int f = tid + g * THREADS;
        int o_l = f >> 3;
        int i_l = f & 7;
        int idx = (oBase + o_l) * IN_DIM + i0 + i_l;
        float4 c0 = reinterpret_cast<const float4*>(coef)[idx * 2];
        float4 c1 = reinterpret_cast<const float4*>(coef)[idx * 2 + 1];
        float sp = __ldg(scale_sp + idx);
        float vals[NROWS];
        vals[0] = c0.x * sp; vals[1] = c0.y * sp; vals[2] = c0.z * sp; vals[3] = c0.w * sp;
        vals[4] = c1.x * sp; vals[5] = c1.y * sp; vals[6] = c1.z * sp; vals[7] = c1.w * sp;
        vals[8] = __ldg(scale_base + idx);
#pragma unroll
        for (int r = 0; r < NROWS; r++) {
            int k = i_l * NROWS + r;
            split_store(sm + OFF_AHI, sm + OFF_ALO, o_l * ASTRIDE + k, vals[r]);
        }
    }
    __syncthreads();

    // ---- mainloop: warp = m-band (o rows warp*16 .. +15), 4 n-tiles of 8 b ----
    int gid = lane >> 2;           // 0..7
    int tq = lane & 3;             // 0..3
    int orow = warp * 16 + gid;

    float c[4][4];
#pragma unroll
    for (int nt = 0; nt < 4; nt++)
#pragma unroll
        for (int q = 0; q < 4; q++) c[nt][q] = 0.0f;

    const u32* Ahi = sm + OFF_AHI;
    const u32* Alo = sm + OFF_ALO;
    const u32* Bhi = sm + OFF_BHI;
    const u32* Blo = sm + OFF_BLO;

#pragma unroll
    for (int ks = 0; ks < KT / 8; ks++) {      // 9 k-steps
        int k0 = ks * 8 + tq;
        u32 ahi[4], alo[4];
        ahi[0] = Ahi[orow * ASTRIDE + k0];
        ahi[1] = Ahi[(orow + 8) * ASTRIDE + k0];
        ahi[2] = Ahi[orow * ASTRIDE + k0 + 4];
        ahi[3] = Ahi[(orow + 8) * ASTRIDE + k0 + 4];
        alo[0] = Alo[orow * ASTRIDE + k0];
        alo[1] = Alo[(orow + 8) * ASTRIDE + k0];
        alo[2] = Alo[orow * ASTRIDE + k0 + 4];
        alo[3] = Alo[(orow + 8) * ASTRIDE + k0 + 4];

#pragma unroll
        for (int nt = 0; nt < 4; nt++) {
            int n = nt * 8 + gid;
            u32 bhi0 = Bhi[k0 * BSTRIDE + n];
            u32 bhi1 = Bhi[(k0 + 4) * BSTRIDE + n];
            u32 blo0 = Blo[k0 * BSTRIDE + n];
            u32 blo1 = Blo[(k0 + 4) * BSTRIDE + n];
            mma_tf32(c[nt], ahi, bhi0, bhi1);     // hi*hi
            mma_tf32(c[nt], ahi, blo0, blo1);     // hi*lo
            mma_tf32(c[nt], alo, bhi0, bhi1);     // lo*hi
        }
    }

    // ---- epilogue: REDG into y (+bias exactly once via split 0) ----
    {
        int o0 = oBase + warp * 16 + gid;
        int o8 = o0 + 8;
        float bw0 = (split == 0) ? __ldg(bias_w + o0) : 0.0f;
        float bw8 = (split == 0) ? __ldg(bias_w + o8) : 0.0f;
#pragma unroll
        for (int nt = 0; nt < 4; nt++) {
            int bcol = nt * 8 + 2 * tq;
            redg_f32(y + bcol * OUT_DIM + o0,       c[nt][0] + bw0);
            redg_f32(y + (bcol + 1) * OUT_DIM + o0, c[nt][1] + bw0);
            redg_f32(y + bcol * OUT_DIM + o8,       c[nt][2] + bw8);
            redg_f32(y + (bcol + 1) * OUT_DIM + o8, c[nt][3] + bw8);
        }
    }
}

extern "C" void kernel_launch(void* const* d_in, const int* in_sizes, int n_in,
                              void* d_out, int out_size) {
    // metadata order: x, grid, coef, bias_w, scale_base, scale_sp
    const float* x          = (const float*)d_in[0];
    const float* grid       = (const float*)d_in[1];
    const float* coef       = (const float*)d_in[2];
    const float* bias_w     = (const float*)d_in[3];
    const float* scale_base = (const float*)d_in[4];
    const float* scale_sp   = (const float*)d_in[5];
    float* y = (float*)d_out;

    cudaFuncSetAttribute(mma_kernel,
                         cudaFuncAttributeMaxDynamicSharedMemorySize, SMEM_BYTES);
    cudaMemsetAsync(y, 0, (size_t)out_size * sizeof(float));
    dim3 g(OUT_DIM / O_TILE, NSPLIT);        // 6 x 96 = 576 blocks
    mma_kernel<<<g, THREADS, SMEM_BYTES>>>(x, grid, coef, scale_sp,
                                           scale_base, bias_w, y);
}